// round 4
// baseline (speedup 1.0000x reference)
#include <cuda_runtime.h>
#include <cuda_bf16.h>
#include <cstdint>
#include <cub/cub.cuh>

// Problem geometry: B=64 samples, n = 512*512 = 2^18 elements per sample.
#define BATCH 64
#define LOGN  18
#define NPS   (1u << LOGN)              // 262144
#define SMASK (NPS - 1u)                // 0x3FFFF
#define TOTN  (BATCH * NPS)             // 16777216

// ---------------------------------------------------------------------------
// Static device scratch (allocation-free per harness rules).
// ---------------------------------------------------------------------------
__device__ __align__(256) unsigned long long g_bufA[TOTN];   // 128 MB
__device__ __align__(256) unsigned long long g_bufB[TOTN];   // 128 MB
__device__ __align__(256) unsigned long long g_bufC[TOTN];   // 128 MB
__device__ __align__(256) unsigned int       g_rank2[TOTN];  // 64 MB: 2*avg_rank per orig idx
__device__ __align__(256) unsigned char      g_temp[64u * 1024u * 1024u]; // CUB temp
__device__ unsigned long long g_sum2[BATCH];
__device__ unsigned int       g_npos[BATCH];

struct SubKeys { uint2 sk[BATCH]; };

// ---------------------------------------------------------------------------
// Threefry-2x32 (20 rounds), matches JAX's threefry2x32_p.
// ---------------------------------------------------------------------------
__host__ __device__ __forceinline__ void tf2x32(uint32_t k0, uint32_t k1,
                                                uint32_t x0, uint32_t x1,
                                                uint32_t& o0, uint32_t& o1)
{
    uint32_t ks2 = k0 ^ k1 ^ 0x1BD11BDAu;
    x0 += k0; x1 += k1;
#define TFR(r) { x0 += x1; x1 = (x1 << (r)) | (x1 >> (32 - (r))); x1 ^= x0; }
    TFR(13) TFR(15) TFR(26) TFR(6)
    x0 += k1;  x1 += ks2 + 1u;
    TFR(17) TFR(29) TFR(16) TFR(24)
    x0 += ks2; x1 += k0 + 2u;
    TFR(13) TFR(15) TFR(26) TFR(6)
    x0 += k0;  x1 += k1 + 3u;
    TFR(17) TFR(29) TFR(16) TFR(24)
    x0 += k1;  x1 += ks2 + 4u;
    TFR(13) TFR(15) TFR(26) TFR(6)
    x0 += ks2; x1 += k0 + 5u;
#undef TFR
    o0 = x0; o1 = x1;
}

// ---------------------------------------------------------------------------
// Kernel: build rank-sort keys: seg(6) | sortable_float(32) | pos(18)
// ---------------------------------------------------------------------------
__global__ void gen_rank_keys(const float* __restrict__ pred,
                              unsigned long long* __restrict__ out)
{
    unsigned int j = blockIdx.x * blockDim.x + threadIdx.x;
    uint32_t u = __float_as_uint(pred[j]);
    u = (u >> 31) ? ~u : (u | 0x80000000u);   // totally-ordered ascending float bits
    unsigned long long seg = (unsigned long long)(j >> LOGN);
    out[j] = (seg << 50) | ((unsigned long long)u << 18) | (j & SMASK);
}

// ---------------------------------------------------------------------------
// Kernel: from sorted rank keys, compute 2*average_rank (tie-averaged) and
// scatter to rank2[seg*n + orig_idx].  2*rank = lo + hi + 1 with 0-based
// searchsorted(left/right); for a run [s,e] this is s + (e+1) + 1.
// ---------------------------------------------------------------------------
__global__ void rank_kernel(const unsigned long long* __restrict__ KR,
                            unsigned int* __restrict__ rank2)
{
    unsigned int j = blockIdx.x * blockDim.x + threadIdx.x;
    unsigned long long k = KR[j];
    unsigned long long hk = k >> 18;          // seg+value bits: runs never cross segments
    unsigned int s = j, e = j;
    while (s > 0u && (KR[s - 1u] >> 18) == hk) --s;       // ties are rare & short
    while (e + 1u < TOTN && (KR[e + 1u] >> 18) == hk) ++e;
    unsigned int orig = (unsigned int)k & SMASK;
    unsigned int twice_rank = (s & SMASK) + (e & SMASK) + 2u;
    rank2[(j & ~SMASK) | orig] = twice_rank;
}

// ---------------------------------------------------------------------------
// Kernel: build shuffle-sort keys for one round.
// JAX partitionable threefry: bits[i] = o0 ^ o1 of threefry(subkey, (0, i)).
// ---------------------------------------------------------------------------
__global__ void gen_shuffle_keys(SubKeys sks, unsigned long long* __restrict__ out)
{
    unsigned int j = blockIdx.x * blockDim.x + threadIdx.x;
    unsigned int b = j >> LOGN;
    unsigned int i = j & SMASK;
    uint2 k = sks.sk[b];
    uint32_t o0, o1;
    tf2x32(k.x, k.y, 0u, i, o0, o1);
    uint32_t bits = o0 ^ o1;
    out[j] = ((unsigned long long)b << 50) | ((unsigned long long)bits << 18) | i;
}

// ---------------------------------------------------------------------------
// Accumulation: per final position i (labels are NOT shuffled):
//   shuffled[i] = pred[ pi1[ pi2[i] ] ]   with pi = low-18-bits of sorted keys
//   if t[i] > 0:  sum2 += 2*rank(orig),  npos += 1
// ---------------------------------------------------------------------------
__global__ void zero_acc()
{
    unsigned int t = threadIdx.x;
    if (t < BATCH) { g_sum2[t] = 0ull; g_npos[t] = 0u; }
}

__global__ void accum_kernel(const unsigned long long* __restrict__ K2,
                             const unsigned long long* __restrict__ K1,
                             const unsigned int* __restrict__ rank2,
                             const int* __restrict__ truth)
{
    unsigned int j = blockIdx.x * blockDim.x + threadIdx.x;
    unsigned long long r = 0ull;
    unsigned int c = 0u;
    if (truth[j] > 0) {
        unsigned int p2   = (unsigned int)K2[j] & SMASK;        // pi2[i]
        unsigned int base = j & ~SMASK;                          // seg * n
        unsigned int orig = (unsigned int)K1[base | p2] & SMASK; // pi1[pi2[i]]
        r = (unsigned long long)rank2[base | orig];
        c = 1u;
    }
    // intra-warp then intra-block reduction; one atomic pair per block
    #pragma unroll
    for (int o = 16; o > 0; o >>= 1) {
        r += __shfl_down_sync(0xffffffffu, r, o);
        c += __shfl_down_sync(0xffffffffu, c, o);
    }
    __shared__ unsigned long long sr[8];
    __shared__ unsigned int      sc[8];
    unsigned int w = threadIdx.x >> 5, l = threadIdx.x & 31u;
    if (l == 0u) { sr[w] = r; sc[w] = c; }
    __syncthreads();
    if (threadIdx.x == 0u) {
        unsigned long long R = 0ull; unsigned int C = 0u;
        #pragma unroll
        for (int i = 0; i < 8; ++i) { R += sr[i]; C += sc[i]; }
        unsigned int b = j >> LOGN;   // blockDim=256 divides 2^18: block is seg-pure
        atomicAdd(&g_sum2[b], R);
        atomicAdd(&g_npos[b], C);
    }
}

__global__ void finalize_kernel(float* __restrict__ out)
{
    int b = threadIdx.x;
    __shared__ double sh[BATCH];
    double auc = 0.0;
    if (b < BATCH) {
        double np  = (double)g_npos[b];
        double nn  = (double)NPS - np;
        double spr = 0.5 * (double)g_sum2[b];          // sum of positive ranks (exact)
        auc = (spr - np * (np + 1.0) * 0.5) / (np * nn);
    }
    sh[b] = auc;
    __syncthreads();
    if (b == 0) {
        double s = 0.0;
        for (int i = 0; i < BATCH; ++i) s += sh[i];
        out[0] = (float)(s / (double)BATCH);
    }
}

// ---------------------------------------------------------------------------
// Host launch (graph-capturable: kernels + CUB sorts only; no alloc/sync).
// ---------------------------------------------------------------------------
extern "C" void kernel_launch(void* const* d_in, const int* in_sizes, int n_in,
                              void* d_out, int out_size)
{
    (void)in_sizes; (void)n_in; (void)out_size;
    const float* pred  = (const float*)d_in[0];
    const int*   truth = (const int*)d_in[1];
    float*       out   = (float*)d_out;

    // Derive the per-sample shuffle subkeys on the host (deterministic, cheap).
    // root = threefry_seed(42) = (0, 42).
    // partitionable split: keys[b] = tf(root, (0, b))
    // _shuffle round r: key, subkey = split(key) -> key'=tf(key,(0,0)), sub=tf(key,(0,1))
    SubKeys s1, s2;
    for (int b = 0; b < BATCH; ++b) {
        uint32_t kb0, kb1, nk0, nk1, a0, a1;
        tf2x32(0u, 42u, 0u, (uint32_t)b, kb0, kb1);   // sample key
        tf2x32(kb0, kb1, 0u, 0u, nk0, nk1);           // carried key after round-1 split
        tf2x32(kb0, kb1, 0u, 1u, a0, a1);             // round-1 subkey
        s1.sk[b] = make_uint2(a0, a1);
        tf2x32(nk0, nk1, 0u, 1u, a0, a1);             // round-2 subkey
        s2.sk[b] = make_uint2(a0, a1);
    }

    unsigned long long *dA, *dB, *dC;
    unsigned int* dRank;
    void* dTemp;
    cudaGetSymbolAddress((void**)&dA, g_bufA);
    cudaGetSymbolAddress((void**)&dB, g_bufB);
    cudaGetSymbolAddress((void**)&dC, g_bufC);
    cudaGetSymbolAddress((void**)&dRank, g_rank2);
    cudaGetSymbolAddress(&dTemp, g_temp);

    const int TPB = 256;
    const unsigned int GRID = TOTN / TPB;   // 65536

    // ---- Phase R: per-sample tie-averaged ranks of pred --------------------
    gen_rank_keys<<<GRID, TPB>>>(pred, dA);
    {
        cub::DoubleBuffer<unsigned long long> db(dA, dB);
        size_t tb = sizeof(g_temp);
        cub::DeviceRadixSort::SortKeys(dTemp, tb, db, (int)TOTN, 18, 56);
        rank_kernel<<<GRID, TPB>>>(db.Current(), dRank);
    }

    // ---- Phase S: two stable sorts by threefry bits = JAX _shuffle ---------
    gen_shuffle_keys<<<GRID, TPB>>>(s1, dA);
    cub::DoubleBuffer<unsigned long long> db1(dA, dB);
    {
        size_t tb = sizeof(g_temp);
        cub::DeviceRadixSort::SortKeys(dTemp, tb, db1, (int)TOTN, 18, 56);
    }
    const unsigned long long* K1 = db1.Current();
    unsigned long long* alt = (K1 == dA) ? dB : dA;

    gen_shuffle_keys<<<GRID, TPB>>>(s2, dC);
    cub::DoubleBuffer<unsigned long long> db2(dC, alt);
    {
        size_t tb = sizeof(g_temp);
        cub::DeviceRadixSort::SortKeys(dTemp, tb, db2, (int)TOTN, 18, 56);
    }
    const unsigned long long* K2 = db2.Current();

    // ---- Phase F: exact integer AUC accumulation + mean --------------------
    zero_acc<<<1, BATCH>>>();
    accum_kernel<<<GRID, TPB>>>(K2, K1, dRank, truth);
    finalize_kernel<<<1, BATCH>>>(out);
}